// round 17
// baseline (speedup 1.0000x reference)
#include <cuda_runtime.h>
#include <math.h>

constexpr int H_   = 768;
constexpr int H4_  = H_ / 4;  // 192 float4 per row
constexpr int NC_  = 8;       // chunks
constexpr int NL_  = 8921;    // labels
constexpr int NN_  = 4;       // notes
constexpr int JB_  = 1115;    // lw bucket width (8921 = 8*1115 + 1)

constexpr int ESEG  = 32;     // segments per encoding chunk (16 rows each)
constexpr int EROWS = 16;
constexpr int LSEG  = 64;     // segments per lw bucket (18 rows each)
constexpr int LROWS = 18;     // 64*18 = 1152 >= 1116
constexpr int ENC_BLOCKS = NC_ * ESEG;          // 256
constexpr int LW_BLOCKS  = NC_ * LSEG;          // 512
constexpr int GRID       = ENC_BLOCKS + LW_BLOCKS;  // 768
constexpr int TPB        = 192;                 // 192 threads * float4 = 768 columns

// Accumulators. Zero at module load; final2_kernel re-zeroes exactly the slots
// it consumed -> invariant "zero on entry to sum_kernel" holds on every replay.
__device__ float g_CS[NC_ * H_];          // per-chunk encoding column sums
__device__ float g_L [NC_ * H_];          // per-bucket lw column sums

__device__ __forceinline__ void redg_add(float* p, float v) {
    asm volatile("red.relaxed.gpu.global.add.f32 [%0], %1;" :: "l"(p), "f"(v) : "memory");
}
__device__ __forceinline__ float ldg_gpu(const float* p) {
    float v;
    asm volatile("ld.relaxed.gpu.global.f32 %0, [%1];" : "=f"(v) : "l"(p) : "memory");
    return v;
}
__device__ __forceinline__ void f4acc(float4& a, float4 b) {
    a.x += b.x; a.y += b.y; a.z += b.z; a.w += b.w;
}

// ---------------- Kernel 1: float4 streaming block sums; early PDL trigger ----------------
__global__ __launch_bounds__(TPB, 8) void sum_kernel(const float* __restrict__ encF,
                                                     const float* __restrict__ lwF) {
    // Early trigger: dependent grid (final2) becomes schedulable once all
    // primary blocks execute this; its wait still blocks until grid completion
    // + memory flush, ordering the REDGs below.
    asm volatile("griddepcontrol.launch_dependents;" ::: "memory");

    const float4* enc = (const float4*)encF;
    const float4* lw  = (const float4*)lwF;
    const int b = blockIdx.x;
    const int t = threadIdx.x;

    if (b < ENC_BLOCKS) {
        int c = b >> 5, s = b & 31;                       // chunk, segment
        const float4* p = enc + (size_t)(c * 512 + s * EROWS) * H4_ + t;
        float4 a0 = make_float4(0,0,0,0), a1 = a0, a2 = a0, a3 = a0;
        #pragma unroll
        for (int r = 0; r < EROWS; r += 4) {
            f4acc(a0, p[(r + 0) * H4_]);
            f4acc(a1, p[(r + 1) * H4_]);
            f4acc(a2, p[(r + 2) * H4_]);
            f4acc(a3, p[(r + 3) * H4_]);
        }
        float4 s4 = make_float4((a0.x + a1.x) + (a2.x + a3.x),
                                (a0.y + a1.y) + (a2.y + a3.y),
                                (a0.z + a1.z) + (a2.z + a3.z),
                                (a0.w + a1.w) + (a2.w + a3.w));
        float* dst = &g_CS[c * H_ + t * 4];
        redg_add(dst + 0, s4.x);
        redg_add(dst + 1, s4.y);
        redg_add(dst + 2, s4.z);
        redg_add(dst + 3, s4.w);
    } else {
        int bb = b - ENC_BLOCKS;
        int c = bb >> 6, s = bb & 63;                     // bucket, segment
        int r0   = c * JB_ + s * LROWS;
        int rend = min(r0 + LROWS, (c == NC_ - 1) ? NL_ : (c + 1) * JB_);
        float4 a0 = make_float4(0,0,0,0), a1 = a0;
        int r = r0;
        for (; r + 2 <= rend; r += 2) {
            f4acc(a0, lw[(size_t)(r + 0) * H4_ + t]);
            f4acc(a1, lw[(size_t)(r + 1) * H4_ + t]);
        }
        if (r < rend) f4acc(a0, lw[(size_t)r * H4_ + t]);
        float4 s4 = make_float4(a0.x + a1.x, a0.y + a1.y,
                                a0.z + a1.z, a0.w + a1.w);
        float* dst = &g_L[c * H_ + t * 4];
        redg_add(dst + 0, s4.x);
        redg_add(dst + 1, s4.y);
        redg_add(dst + 2, s4.z);
        redg_add(dst + 3, s4.w);
    }
}

// ---------------- Kernel 2 (PDL): prologue overlaps sum_kernel; wait; combine ----------------
__global__ __launch_bounds__(128) void final2_kernel(const float* __restrict__ lw,
                                                     const void* __restrict__ idsRaw,
                                                     float* __restrict__ out) {
    const int h = blockIdx.x * 128 + threadIdx.x;   // one column per thread, 768 total

    // ---- prologue: everything independent of the accumulators ----
    float bnd[NC_ - 1];
    #pragma unroll
    for (int k = 1; k < NC_; ++k)
        bnd[k - 1] = lw[(size_t)(JB_ * k) * H_ + h];

    // note_end_chunk_ids: detect int64 vs int32 layout
    const int* w = (const int*)idsRaw;
    int ids[NN_];
    {
        bool is64 = true;
        int v[NN_];
        #pragma unroll
        for (int i = 0; i < NN_; ++i) {
            int lo = w[2 * i], hi = w[2 * i + 1];
            v[i] = lo;
            if (hi != 0 || lo < 0 || lo >= NC_) is64 = false;
        }
        #pragma unroll
        for (int i = 0; i + 1 < NN_; ++i)
            if (v[i] > v[i + 1]) is64 = false;
        #pragma unroll
        for (int i = 0; i < NN_; ++i) ids[i] = is64 ? v[i] : w[i];
    }

    // softmax weight table (4 notes x 8 chunks) — accumulator-independent
    float W[NN_][NC_];
    #pragma unroll
    for (int c = 0; c < NC_; ++c) {
        int cnt = 0;
        #pragma unroll
        for (int i = 0; i < NN_; ++i) cnt += (ids[i] < c) ? 1 : 0;
        #pragma unroll
        for (int n = 0; n < NN_; ++n) {
            bool un = (ids[n] < c);
            W[n][c] = (cnt > 0) ? (un ? 1.0f / (float)cnt : 0.0f) : 0.25f;
        }
    }

    // ---- PDL gate: block until sum_kernel completes & its REDGs are visible ----
    asm volatile("griddepcontrol.wait;" ::: "memory");

    float CS[NC_], L[NC_];
    #pragma unroll
    for (int c = 0; c < NC_; ++c) {
        CS[c] = ldg_gpu(&g_CS[c * H_ + h]);
        L[c]  = ldg_gpu(&g_L [c * H_ + h]);
    }
    // Re-zero for the next replay: each thread clears exactly the slots it read.
    #pragma unroll
    for (int c = 0; c < NC_; ++c) {
        g_CS[c * H_ + h] = 0.f;
        g_L [c * H_ + h] = 0.f;
    }

    float Ptot = 0.f;
    #pragma unroll
    for (int c = 0; c < NC_; ++c) Ptot += CS[c];

    #pragma unroll
    for (int n = 0; n < NN_; ++n) {
        float dot = 0.f;
        #pragma unroll
        for (int c = 0; c < NC_; ++c) dot += W[n][c] * L[c];
        float score = Ptot * dot;

        // boundary corrections: j = 1115k straddles chunks (k-1, k) at prefix P[512k]
        float P = 0.f;
        #pragma unroll
        for (int k = 1; k < NC_; ++k) {
            P += CS[k - 1];
            float wd = W[n][k - 1] - W[n][k];
            score += wd * bnd[k - 1] * P;
        }
        out[n * H_ + h] = 1.0f / (1.0f + expf(-score));
    }
}

extern "C" void kernel_launch(void* const* d_in, const int* in_sizes, int n_in,
                              void* d_out, int out_size) {
    const float* enc = (const float*)d_in[0];   // encoding (4096, 768)
    // d_in[1] = label_queries: provably unused (softmax over the note axis cancels scores)
    const float* lw  = (const float*)d_in[2];   // label_weights flat (768*8921)
    const void*  ids = d_in[3];                 // note_end_chunk_ids (4, int32 or int64)
    float* out = (float*)d_out;                 // (4, 768) float32

    sum_kernel<<<GRID, TPB>>>(enc, lw);

    // PDL launch: final2 schedulable once all sum_kernel blocks trigger; parks
    // at griddepcontrol.wait until sum_kernel completes (memory flush included).
    cudaLaunchConfig_t cfg = {};
    cfg.gridDim  = dim3(H_ / 128);
    cfg.blockDim = dim3(128);
    cfg.dynamicSmemBytes = 0;
    cfg.stream = 0;                              // same (legacy default) stream as <<<>>>
    cudaLaunchAttribute attr[1];
    attr[0].id = cudaLaunchAttributeProgrammaticStreamSerialization;
    attr[0].val.programmaticStreamSerializationAllowed = 1;
    cfg.attrs    = attr;
    cfg.numAttrs = 1;
    cudaError_t e = cudaLaunchKernelEx(&cfg, final2_kernel, lw, ids, (float*)out);
    if (e != cudaSuccess) {
        (void)cudaGetLastError();                // clear sticky error from rejected config
        // Fallback: plain serialized launch (correct either way)
        final2_kernel<<<H_ / 128, 128>>>(lw, ids, (float*)out);
    }
}